// round 1
// baseline (speedup 1.0000x reference)
#include <cuda_runtime.h>
#include <cstdint>

// ---------------------------------------------------------------------------
// GridPooling: key = (batch<<21)|(gx<<14)|(gy<<7)|gz with g = grid_coord>>1
// Dense histogram over key space H = 4*128^3, rank-scan for jnp.unique order,
// segment-mean of 64-ch features + coords, then GEMM (mean_feat @ W + b).
// ---------------------------------------------------------------------------

#define MAXN     1000000
#define KDIM     128
#define NBATCH   4
#define HSIZE    (NBATCH * KDIM * KDIM * KDIM)   // 8,388,608
#define SCAN_T   512
#define SCAN_E   8
#define SCAN_BLK (SCAN_T * SCAN_E)               // 4096
#define NSCANBLK (HSIZE / SCAN_BLK)              // 2048

__device__ int   g_keys[MAXN];
__device__ int   g_hist[HSIZE];
__device__ int   g_rank[HSIZE];
__device__ float g_fsum[(size_t)MAXN * 64];
__device__ int   g_blockSums[NSCANBLK];
__device__ int   g_U[1];

typedef unsigned long long ull;

// ---------------- small kernels ----------------

__global__ void init_defaults_kernel(float* grid_out, float* batch_out, int N) {
    int i = blockIdx.x * blockDim.x + threadIdx.x;
    if (i < N) {
        batch_out[i] = -1.0f;
        grid_out[3 * i + 0] = 127.0f;
        grid_out[3 * i + 1] = 127.0f;
        grid_out[3 * i + 2] = 127.0f;
    }
}

__global__ void compute_keys_kernel(const int* __restrict__ grid_coord,
                                    const int* __restrict__ batch, int N) {
    int i = blockIdx.x * blockDim.x + threadIdx.x;
    if (i < N) {
        int gx = grid_coord[3 * i + 0] >> 1;
        int gy = grid_coord[3 * i + 1] >> 1;
        int gz = grid_coord[3 * i + 2] >> 1;
        int b  = batch[i];
        int key = (b << 21) | (gx << 14) | (gy << 7) | gz;
        g_keys[i] = key;
        atomicAdd(&g_hist[key], 1);
    }
}

// pass 1: per-block count of occupied hist entries
__global__ void hist_pass1_kernel() {
    __shared__ int sm[SCAN_T];
    int t = threadIdx.x;
    int idx4 = blockIdx.x * (SCAN_BLK / 4) + t * 2;
    const int4* h4 = reinterpret_cast<const int4*>(g_hist);
    int4 a = h4[idx4];
    int4 b = h4[idx4 + 1];
    int s = (a.x > 0) + (a.y > 0) + (a.z > 0) + (a.w > 0)
          + (b.x > 0) + (b.y > 0) + (b.z > 0) + (b.w > 0);
    sm[t] = s;
    __syncthreads();
    for (int off = SCAN_T / 2; off > 0; off >>= 1) {
        if (t < off) sm[t] += sm[t + off];
        __syncthreads();
    }
    if (t == 0) g_blockSums[blockIdx.x] = sm[0];
}

// pass 2: exclusive scan of 2048 block sums (single block, 1024 threads)
__global__ void scan_blocksums_kernel() {
    __shared__ int sm[1024];
    int t = threadIdx.x;
    int v0 = g_blockSums[2 * t];
    int v1 = g_blockSums[2 * t + 1];
    sm[t] = v0 + v1;
    __syncthreads();
    for (int off = 1; off < 1024; off <<= 1) {
        int x = (t >= off) ? sm[t - off] : 0;
        __syncthreads();
        sm[t] += x;
        __syncthreads();
    }
    int pre = (t > 0) ? sm[t - 1] : 0;
    g_blockSums[2 * t]     = pre;
    g_blockSums[2 * t + 1] = pre + v0;
    if (t == 1023) g_U[0] = sm[1023];
}

// pass 3: assign ranks, scatter unique decode (grid/batch/counts), fill g_rank
__global__ void hist_pass3_kernel(float* __restrict__ grid_out,
                                  float* __restrict__ batch_out,
                                  float* __restrict__ counts_out) {
    __shared__ int sm[SCAN_T];
    int t = threadIdx.x;
    int key0 = blockIdx.x * SCAN_BLK + t * SCAN_E;
    int idx4 = key0 >> 2;
    const int4* h4 = reinterpret_cast<const int4*>(g_hist);
    int4 a = h4[idx4];
    int4 b = h4[idx4 + 1];
    int c[8] = {a.x, a.y, a.z, a.w, b.x, b.y, b.z, b.w};
    int s = 0;
#pragma unroll
    for (int j = 0; j < 8; j++) s += (c[j] > 0);
    sm[t] = s;
    __syncthreads();
    for (int off = 1; off < SCAN_T; off <<= 1) {
        int x = (t >= off) ? sm[t - off] : 0;
        __syncthreads();
        sm[t] += x;
        __syncthreads();
    }
    int r = g_blockSums[blockIdx.x] + ((t > 0) ? sm[t - 1] : 0);
#pragma unroll
    for (int j = 0; j < 8; j++) {
        if (c[j] > 0) {
            int key = key0 + j;
            g_rank[key] = r;
            int bb = key >> 21;
            int xx = (key >> 14) & 127;
            int yy = (key >> 7) & 127;
            int zz = key & 127;
            grid_out[3 * r + 0] = (float)xx;
            grid_out[3 * r + 1] = (float)yy;
            grid_out[3 * r + 2] = (float)zz;
            batch_out[r] = (float)bb;
            counts_out[r] = (float)c[j];
            r++;
        }
    }
}

// scatter: one warp per point. cluster out, coord sums, 64-ch feature sums.
__global__ void scatter_points_kernel(const float* __restrict__ feat,
                                      const float* __restrict__ coord,
                                      float* __restrict__ coord_out,
                                      float* __restrict__ cluster_out, int N) {
    int warp = (blockIdx.x * blockDim.x + threadIdx.x) >> 5;
    int lane = threadIdx.x & 31;
    if (warp >= N) return;
    int c = 0;
    if (lane == 0) c = g_rank[g_keys[warp]];
    c = __shfl_sync(0xffffffffu, c, 0);
    const float* f = feat + (size_t)warp * 64;
    float* fs = g_fsum + (size_t)c * 64;
    atomicAdd(&fs[lane],      f[lane]);
    atomicAdd(&fs[lane + 32], f[lane + 32]);
    if (lane < 3) atomicAdd(&coord_out[3 * c + lane], coord[3 * warp + lane]);
    if (lane == 0) cluster_out[warp] = (float)c;
}

__global__ void coord_divide_kernel(float* __restrict__ coord_out,
                                    const float* __restrict__ counts_out, int N) {
    int i = blockIdx.x * blockDim.x + threadIdx.x;
    if (i < N) {
        float cnt = counts_out[i];
        if (cnt > 1.5f) {
            float inv = 1.0f / cnt;
            coord_out[3 * i + 0] *= inv;
            coord_out[3 * i + 1] *= inv;
            coord_out[3 * i + 2] *= inv;
        }
    }
}

// ---------------- GEMM: out[r] = fsum[r] @ W * (1/cnt) + b  (128x128 tile) ----

__device__ __forceinline__ ull pack2(float x) {
    ull r;
    asm("mov.b64 %0, {%1, %1};" : "=l"(r) : "f"(x));
    return r;
}
__device__ __forceinline__ ull packpair(float x, float y) {
    ull r;
    asm("mov.b64 %0, {%1, %2};" : "=l"(r) : "f"(x), "f"(y));
    return r;
}
__device__ __forceinline__ void fma2(ull& d, ull a, ull b) {
    asm("fma.rn.f32x2 %0, %1, %2, %0;" : "+l"(d) : "l"(a), "l"(b));
}
__device__ __forceinline__ float2 unpack2(ull v) {
    float x, y;
    asm("mov.b64 {%0, %1}, %2;" : "=f"(x), "=f"(y) : "l"(v));
    return make_float2(x, y);
}

#define ASTRIDE 132
#define GEMM_SMEM ((64 * ASTRIDE + 64 * 128) * 4)

__global__ __launch_bounds__(256) void gemm_kernel(const float* __restrict__ Wg,
                                                   const float* __restrict__ bias,
                                                   const float* __restrict__ counts,
                                                   float* __restrict__ out, int N) {
    extern __shared__ float smem[];
    float* As = smem;                 // [64][ASTRIDE] transposed A
    float* Ws = smem + 64 * ASTRIDE;  // [64][128]
    int tid = threadIdx.x;
    int rb = blockIdx.x * 128;
    int U = g_U[0];

    if (rb >= U) {  // tail tile: everything is padding -> zeros
#pragma unroll
        for (int q = 0; q < 16; q++) {
            int t = q * 256 + tid;
            int row = rb + (t >> 5);
            int cq = t & 31;
            if (row < N)
                reinterpret_cast<float4*>(out + (size_t)row * 128)[cq] =
                    make_float4(0.f, 0.f, 0.f, 0.f);
        }
        return;
    }

#pragma unroll
    for (int q = 0; q < 8; q++)
        reinterpret_cast<float4*>(Ws)[q * 256 + tid] =
            reinterpret_cast<const float4*>(Wg)[q * 256 + tid];

#pragma unroll
    for (int q = 0; q < 8; q++) {
        int t = q * 256 + tid;
        int row = t >> 4;
        int kq = t & 15;
        float4 v = make_float4(0.f, 0.f, 0.f, 0.f);
        int gr = rb + row;
        if (gr < N)
            v = reinterpret_cast<const float4*>(g_fsum + (size_t)gr * 64)[kq];
        As[(kq * 4 + 0) * ASTRIDE + row] = v.x;
        As[(kq * 4 + 1) * ASTRIDE + row] = v.y;
        As[(kq * 4 + 2) * ASTRIDE + row] = v.z;
        As[(kq * 4 + 3) * ASTRIDE + row] = v.w;
    }
    __syncthreads();

    int ry = tid >> 4;  // row group 0..15 (8 rows each)
    int cx = tid & 15;  // col group 0..15 (8 cols each)

    ull acc[8][4];
#pragma unroll
    for (int r = 0; r < 8; r++)
#pragma unroll
        for (int p = 0; p < 4; p++) acc[r][p] = 0ull;

#pragma unroll 4
    for (int k = 0; k < 64; k++) {
        float4 a0 = *reinterpret_cast<float4*>(As + k * ASTRIDE + ry * 8);
        float4 a1 = *reinterpret_cast<float4*>(As + k * ASTRIDE + ry * 8 + 4);
        float4 b0 = *reinterpret_cast<float4*>(Ws + k * 128 + cx * 8);
        float4 b1 = *reinterpret_cast<float4*>(Ws + k * 128 + cx * 8 + 4);
        ull bp0 = packpair(b0.x, b0.y);
        ull bp1 = packpair(b0.z, b0.w);
        ull bp2 = packpair(b1.x, b1.y);
        ull bp3 = packpair(b1.z, b1.w);
        float av[8] = {a0.x, a0.y, a0.z, a0.w, a1.x, a1.y, a1.z, a1.w};
#pragma unroll
        for (int r = 0; r < 8; r++) {
            ull ap = pack2(av[r]);
            fma2(acc[r][0], ap, bp0);
            fma2(acc[r][1], ap, bp1);
            fma2(acc[r][2], ap, bp2);
            fma2(acc[r][3], ap, bp3);
        }
    }

    float4 bv0 = reinterpret_cast<const float4*>(bias)[cx * 2];
    float4 bv1 = reinterpret_cast<const float4*>(bias)[cx * 2 + 1];
    float bv[8] = {bv0.x, bv0.y, bv0.z, bv0.w, bv1.x, bv1.y, bv1.z, bv1.w};

#pragma unroll
    for (int r = 0; r < 8; r++) {
        int gr = rb + ry * 8 + r;
        if (gr >= N) continue;
        float cnt = counts[gr];
        float scale = (cnt > 0.f) ? (1.0f / cnt) : 0.f;
        float bon = (cnt > 0.f) ? 1.0f : 0.f;
        float o[8];
#pragma unroll
        for (int p = 0; p < 4; p++) {
            float2 f = unpack2(acc[r][p]);
            o[2 * p] = f.x;
            o[2 * p + 1] = f.y;
        }
#pragma unroll
        for (int j = 0; j < 8; j++) o[j] = o[j] * scale + bv[j] * bon;
        float4* op = reinterpret_cast<float4*>(out + (size_t)gr * 128 + cx * 8);
        op[0] = make_float4(o[0], o[1], o[2], o[3]);
        op[1] = make_float4(o[4], o[5], o[6], o[7]);
    }
}

// ---------------- launch ----------------

extern "C" void kernel_launch(void* const* d_in, const int* in_sizes, int n_in,
                              void* d_out, int out_size) {
    const float* feat       = (const float*)d_in[0];
    const float* coord      = (const float*)d_in[1];
    const int*   grid_coord = (const int*)d_in[2];
    const int*   batch      = (const int*)d_in[3];
    const float* W          = (const float*)d_in[4];
    const float* bias       = (const float*)d_in[5];
    int N = in_sizes[3];
    if (N > MAXN) N = MAXN;

    float* out         = (float*)d_out;
    float* feat_out    = out;
    float* coord_out   = out + (size_t)N * 128;
    float* grid_out    = coord_out + (size_t)N * 3;
    float* batch_out   = grid_out + (size_t)N * 3;
    float* cluster_out = batch_out + N;
    float* counts_out  = cluster_out + N;

    void *p_hist, *p_fsum;
    cudaGetSymbolAddress(&p_hist, g_hist);
    cudaGetSymbolAddress(&p_fsum, g_fsum);

    cudaMemsetAsync(p_hist, 0, (size_t)HSIZE * sizeof(int));
    cudaMemsetAsync(p_fsum, 0, (size_t)N * 64 * sizeof(float));
    cudaMemsetAsync(coord_out, 0, (size_t)N * 3 * sizeof(float));
    cudaMemsetAsync(counts_out, 0, (size_t)N * sizeof(float));

    int tb = 256;
    init_defaults_kernel<<<(N + tb - 1) / tb, tb>>>(grid_out, batch_out, N);
    compute_keys_kernel<<<(N + tb - 1) / tb, tb>>>(grid_coord, batch, N);
    hist_pass1_kernel<<<NSCANBLK, SCAN_T>>>();
    scan_blocksums_kernel<<<1, 1024>>>();
    hist_pass3_kernel<<<NSCANBLK, SCAN_T>>>(grid_out, batch_out, counts_out);
    scatter_points_kernel<<<(N + 7) / 8, 256>>>(feat, coord, coord_out,
                                                cluster_out, N);
    coord_divide_kernel<<<(N + tb - 1) / tb, tb>>>(coord_out, counts_out, N);

    static int smem_set = 0;
    if (!smem_set) {
        cudaFuncSetAttribute(gemm_kernel,
                             cudaFuncAttributeMaxDynamicSharedMemorySize,
                             GEMM_SMEM);
        smem_set = 1;
    }
    gemm_kernel<<<(N + 127) / 128, 256, GEMM_SMEM>>>(W, bias, counts_out,
                                                     feat_out, N);
}

// round 3
// speedup vs baseline: 1.3124x; 1.3124x over previous
#include <cuda_runtime.h>
#include <cuda_bf16.h>
#include <cstdint>

// ---------------------------------------------------------------------------
// GridPooling: key = (batch<<21)|(gx<<14)|(gy<<7)|gz with g = grid_coord>>1
// Dense hist over H = 4*128^3, pair rank/offset scan -> CSR point lists,
// then bf16 hi/lo split HMMA GEMM (mma.sync) with fused gather-mean.
// ---------------------------------------------------------------------------

#define MAXN     1000000
#define KDIM     128
#define NBATCH   4
#define HSIZE    (NBATCH * KDIM * KDIM * KDIM)   // 8,388,608
#define SCAN_T   512
#define SCAN_E   8
#define SCAN_BLK (SCAN_T * SCAN_E)               // 4096
#define NSCANBLK (HSIZE / SCAN_BLK)              // 2048

typedef unsigned long long ull;

__device__ int  g_keys[MAXN];
__device__ int  g_hist[HSIZE];
__device__ int  g_rank[HSIZE];
__device__ int  g_start[MAXN + 1];
__device__ int  g_cursor[MAXN];
__device__ int  g_pidx[MAXN];
__device__ ull  g_blk[NSCANBLK];
__device__ int  g_U[1];
// packed bf16 W tiles: B_hi words [n*36+kp] (n<128, kp<32), B_lo at +4608 words
__device__ uint4 g_Bpack4[2304];

// ---------------- small kernels ----------------

__global__ void init_defaults_kernel(float* grid_out, float* batch_out,
                                     float* counts_out, int N) {
    int i = blockIdx.x * blockDim.x + threadIdx.x;
    if (i < N) {
        batch_out[i] = -1.0f;
        grid_out[3 * i + 0] = 127.0f;
        grid_out[3 * i + 1] = 127.0f;
        grid_out[3 * i + 2] = 127.0f;
        counts_out[i] = 0.0f;
    }
}

__global__ void compute_keys_kernel(const int* __restrict__ grid_coord,
                                    const int* __restrict__ batch, int N) {
    int i = blockIdx.x * blockDim.x + threadIdx.x;
    if (i < N) {
        int gx = grid_coord[3 * i + 0] >> 1;
        int gy = grid_coord[3 * i + 1] >> 1;
        int gz = grid_coord[3 * i + 2] >> 1;
        int key = (batch[i] << 21) | (gx << 14) | (gy << 7) | gz;
        g_keys[i] = key;
        atomicAdd(&g_hist[key], 1);
    }
}

// pack W[64][128] -> bf16 hi/lo tiles B^T[n][kp] in stride-36-word layout
__global__ void bpack_kernel(const float* __restrict__ Wg) {
    uint32_t* bp = reinterpret_cast<uint32_t*>(g_Bpack4);
    int tid = threadIdx.x;
#pragma unroll
    for (int q = 0; q < 16; q++) {
        int cell = q * 256 + tid;      // 4096 cells: n in [0,128), kp in [0,32)
        int n = cell >> 5;
        int kp = cell & 31;
        float w0 = Wg[(2 * kp) * 128 + n];
        float w1 = Wg[(2 * kp + 1) * 128 + n];
        __nv_bfloat16 h0 = __float2bfloat16(w0), h1 = __float2bfloat16(w1);
        __nv_bfloat16 l0 = __float2bfloat16(w0 - __bfloat162float(h0));
        __nv_bfloat16 l1 = __float2bfloat16(w1 - __bfloat162float(h1));
        uint32_t hp = ((uint32_t)__bfloat16_as_ushort(h1) << 16) | __bfloat16_as_ushort(h0);
        uint32_t lp = ((uint32_t)__bfloat16_as_ushort(l1) << 16) | __bfloat16_as_ushort(l0);
        bp[n * 36 + kp] = hp;
        bp[4608 + n * 36 + kp] = lp;
    }
}

// pass 1: per-block (occupied, total-count) packed as (occ<<32)|cnt
__global__ void hist_pass1_kernel() {
    __shared__ ull sm[SCAN_T];
    int t = threadIdx.x;
    int idx4 = blockIdx.x * (SCAN_BLK / 4) + t * 2;
    const int4* h4 = reinterpret_cast<const int4*>(g_hist);
    int4 a = h4[idx4];
    int4 b = h4[idx4 + 1];
    int occ = (a.x > 0) + (a.y > 0) + (a.z > 0) + (a.w > 0)
            + (b.x > 0) + (b.y > 0) + (b.z > 0) + (b.w > 0);
    int cnt = a.x + a.y + a.z + a.w + b.x + b.y + b.z + b.w;
    sm[t] = ((ull)occ << 32) | (unsigned)cnt;
    __syncthreads();
    for (int off = SCAN_T / 2; off > 0; off >>= 1) {
        if (t < off) sm[t] += sm[t + off];
        __syncthreads();
    }
    if (t == 0) g_blk[blockIdx.x] = sm[0];
}

// pass 2: exclusive pair-scan of 2048 block sums
__global__ void scan_blocksums_kernel() {
    __shared__ ull sm[1024];
    int t = threadIdx.x;
    ull v0 = g_blk[2 * t];
    ull v1 = g_blk[2 * t + 1];
    sm[t] = v0 + v1;
    __syncthreads();
    for (int off = 1; off < 1024; off <<= 1) {
        ull x = (t >= off) ? sm[t - off] : 0ull;
        __syncthreads();
        sm[t] += x;
        __syncthreads();
    }
    ull pre = (t > 0) ? sm[t - 1] : 0ull;
    g_blk[2 * t]     = pre;
    g_blk[2 * t + 1] = pre + v0;
    if (t == 1023) g_U[0] = (int)(sm[1023] >> 32);
}

// pass 3: assign rank + point offsets, scatter unique decode
__global__ void hist_pass3_kernel(float* __restrict__ grid_out,
                                  float* __restrict__ batch_out,
                                  float* __restrict__ counts_out) {
    __shared__ ull sm[SCAN_T];
    int t = threadIdx.x;
    int key0 = blockIdx.x * SCAN_BLK + t * SCAN_E;
    int idx4 = key0 >> 2;
    const int4* h4 = reinterpret_cast<const int4*>(g_hist);
    int4 a = h4[idx4];
    int4 b = h4[idx4 + 1];
    int c[8] = {a.x, a.y, a.z, a.w, b.x, b.y, b.z, b.w};
    int occ = 0, cnt = 0;
#pragma unroll
    for (int j = 0; j < 8; j++) { occ += (c[j] > 0); cnt += c[j]; }
    sm[t] = ((ull)occ << 32) | (unsigned)cnt;
    __syncthreads();
    for (int off = 1; off < SCAN_T; off <<= 1) {
        ull x = (t >= off) ? sm[t - off] : 0ull;
        __syncthreads();
        sm[t] += x;
        __syncthreads();
    }
    ull base = g_blk[blockIdx.x] + ((t > 0) ? sm[t - 1] : 0ull);
    int r = (int)(base >> 32);
    int o = (int)(base & 0xffffffffu);
#pragma unroll
    for (int j = 0; j < 8; j++) {
        if (c[j] > 0) {
            int key = key0 + j;
            g_rank[key] = r;
            g_start[r]  = o;
            g_cursor[r] = o;
            grid_out[3 * r + 0] = (float)((key >> 14) & 127);
            grid_out[3 * r + 1] = (float)((key >> 7) & 127);
            grid_out[3 * r + 2] = (float)(key & 127);
            batch_out[r]  = (float)(key >> 21);
            counts_out[r] = (float)c[j];
            r++;
            o += c[j];
        }
    }
}

// scatter point indices into CSR lists
__global__ void scatter_pidx_kernel(float* __restrict__ cluster_out, int N) {
    int i = blockIdx.x * blockDim.x + threadIdx.x;
    if (i < N) {
        int c = g_rank[g_keys[i]];
        int pos = atomicAdd(&g_cursor[c], 1);
        g_pidx[pos] = i;
        cluster_out[i] = (float)c;
    }
}

// per-cluster coord mean via CSR gather
__global__ void coord_mean_kernel(const float* __restrict__ coord,
                                  const float* __restrict__ counts,
                                  float* __restrict__ coord_out, int N) {
    int r = blockIdx.x * blockDim.x + threadIdx.x;
    if (r >= N) return;
    int U = g_U[0];
    float x = 0.f, y = 0.f, z = 0.f;
    if (r < U) {
        int s = g_start[r];
        int c = (int)counts[r];
        for (int j = 0; j < c; j++) {
            int p = g_pidx[s + j];
            x += coord[3 * p + 0];
            y += coord[3 * p + 1];
            z += coord[3 * p + 2];
        }
        float inv = 1.0f / (float)c;
        x *= inv; y *= inv; z *= inv;
    }
    coord_out[3 * r + 0] = x;
    coord_out[3 * r + 1] = y;
    coord_out[3 * r + 2] = z;
}

// ---------------- HMMA GEMM with fused gather-mean ----------------
// out[r] = mean_feat[r] @ W + b via bf16 hi/lo split (3 products).
// A tiles [128 rows][32 kpairs] words, stride 36 words (bank-conflict-free).
// B tiles identical layout, precomputed in g_Bpack4.

#define GEMM_SMEM 73728   // 18432 words: A_hi 0, A_lo 4608, B_hi 9216, B_lo 13824

__device__ __forceinline__ void mma_bf16(float* c, const uint32_t* a,
                                         uint32_t b0, uint32_t b1) {
    asm volatile(
        "mma.sync.aligned.m16n8k16.row.col.f32.bf16.bf16.f32 "
        "{%0,%1,%2,%3}, {%4,%5,%6,%7}, {%8,%9}, {%0,%1,%2,%3};"
        : "+f"(c[0]), "+f"(c[1]), "+f"(c[2]), "+f"(c[3])
        : "r"(a[0]), "r"(a[1]), "r"(a[2]), "r"(a[3]), "r"(b0), "r"(b1));
}

__global__ __launch_bounds__(256) void gemm_kernel(const float* __restrict__ bias,
                                                   const float* __restrict__ feat,
                                                   const float* __restrict__ counts,
                                                   float* __restrict__ out, int N) {
    extern __shared__ uint32_t sm[];
    int tid = threadIdx.x;
    int rb = blockIdx.x * 128;
    int U = g_U[0];

    if (rb >= U) {  // pure padding tile -> zeros
#pragma unroll
        for (int q = 0; q < 16; q++) {
            int t = q * 256 + tid;
            int row = rb + (t >> 5);
            if (row < N)
                reinterpret_cast<float4*>(out + (size_t)row * 128)[t & 31] =
                    make_float4(0.f, 0.f, 0.f, 0.f);
        }
        return;
    }

    // copy packed B tiles (L2-resident, coalesced)
    {
        uint4* dst = reinterpret_cast<uint4*>(sm + 9216);
#pragma unroll
        for (int q = 0; q < 9; q++) dst[q * 256 + tid] = g_Bpack4[q * 256 + tid];
    }

    // A: gather-mean feat rows per cluster; thread = (row, half of 64 ch)
    {
        int row = tid >> 1;
        int half = tid & 1;
        int gr = rb + row;
        float acc[32];
#pragma unroll
        for (int q = 0; q < 32; q++) acc[q] = 0.f;
        float inv = 0.f;
        if (gr < U) {
            int s = g_start[gr];
            int c = (int)counts[gr];
            inv = 1.0f / (float)c;
            for (int j = 0; j < c; j++) {
                int p = g_pidx[s + j];
                const float4* f =
                    reinterpret_cast<const float4*>(feat + (size_t)p * 64 + half * 32);
#pragma unroll
                for (int q = 0; q < 8; q++) {
                    float4 v = f[q];
                    acc[4 * q + 0] += v.x;
                    acc[4 * q + 1] += v.y;
                    acc[4 * q + 2] += v.z;
                    acc[4 * q + 3] += v.w;
                }
            }
        }
        int base = row * 36 + half * 16;
#pragma unroll
        for (int c2 = 0; c2 < 16; c2++) {
            float x0 = acc[2 * c2] * inv, x1 = acc[2 * c2 + 1] * inv;
            __nv_bfloat16 h0 = __float2bfloat16(x0), h1 = __float2bfloat16(x1);
            __nv_bfloat16 l0 = __float2bfloat16(x0 - __bfloat162float(h0));
            __nv_bfloat16 l1 = __float2bfloat16(x1 - __bfloat162float(h1));
            sm[base + c2] = ((uint32_t)__bfloat16_as_ushort(h1) << 16) |
                            __bfloat16_as_ushort(h0);
            sm[4608 + base + c2] = ((uint32_t)__bfloat16_as_ushort(l1) << 16) |
                                   __bfloat16_as_ushort(l0);
        }
    }
    __syncthreads();

    // warp tiling: 4 warps along M x 2 along N; warp tile 32x64
    int wid = tid >> 5, lane = tid & 31;
    int g = lane >> 2, tig = lane & 3;
    int wm = wid & 3, wn = wid >> 2;
    int arow = wm * 32 + g;
    int bn = wn * 64 + g;

    float c[2][8][4];
#pragma unroll
    for (int mt = 0; mt < 2; mt++)
#pragma unroll
        for (int j = 0; j < 8; j++)
#pragma unroll
            for (int q = 0; q < 4; q++) c[mt][j][q] = 0.f;

#pragma unroll
    for (int p = 0; p < 3; p++) {
        const uint32_t* A = sm + ((p < 2) ? 0 : 4608);
        const uint32_t* B = sm + ((p == 1) ? 13824 : 9216);
#pragma unroll
        for (int ks = 0; ks < 4; ks++) {
            int kb = ks * 8 + tig;
            uint32_t a[2][4];
#pragma unroll
            for (int mt = 0; mt < 2; mt++) {
                int r = (arow + mt * 16) * 36;
                a[mt][0] = A[r + kb];
                a[mt][1] = A[r + 8 * 36 + kb];
                a[mt][2] = A[r + kb + 4];
                a[mt][3] = A[r + 8 * 36 + kb + 4];
            }
#pragma unroll
            for (int j = 0; j < 8; j++) {
                int nb = (bn + j * 8) * 36;
                uint32_t b0 = B[nb + kb];
                uint32_t b1 = B[nb + kb + 4];
                mma_bf16(c[0][j], a[0], b0, b1);
                mma_bf16(c[1][j], a[1], b0, b1);
            }
        }
    }

    // epilogue: +bias if gr < U else 0; direct STG.64
#pragma unroll
    for (int mt = 0; mt < 2; mt++) {
#pragma unroll
        for (int half = 0; half < 2; half++) {
            int gr = rb + wm * 32 + mt * 16 + g + half * 8;
            if (gr >= N) continue;
            bool on = gr < U;
#pragma unroll
            for (int j = 0; j < 8; j++) {
                int col = wn * 64 + j * 8 + tig * 2;
                float2 v;
                if (on) {
                    float2 bv = *reinterpret_cast<const float2*>(bias + col);
                    v.x = c[mt][j][half * 2 + 0] + bv.x;
                    v.y = c[mt][j][half * 2 + 1] + bv.y;
                } else {
                    v = make_float2(0.f, 0.f);
                }
                *reinterpret_cast<float2*>(out + (size_t)gr * 128 + col) = v;
            }
        }
    }
}

// ---------------- launch ----------------

extern "C" void kernel_launch(void* const* d_in, const int* in_sizes, int n_in,
                              void* d_out, int out_size) {
    const float* feat       = (const float*)d_in[0];
    const float* coord      = (const float*)d_in[1];
    const int*   grid_coord = (const int*)d_in[2];
    const int*   batch      = (const int*)d_in[3];
    const float* W          = (const float*)d_in[4];
    const float* bias       = (const float*)d_in[5];
    int N = in_sizes[3];
    if (N > MAXN) N = MAXN;

    float* out         = (float*)d_out;
    float* feat_out    = out;
    float* coord_out   = out + (size_t)N * 128;
    float* grid_out    = coord_out + (size_t)N * 3;
    float* batch_out   = grid_out + (size_t)N * 3;
    float* cluster_out = batch_out + N;
    float* counts_out  = cluster_out + N;

    void* p_hist;
    cudaGetSymbolAddress(&p_hist, g_hist);
    cudaMemsetAsync(p_hist, 0, (size_t)HSIZE * sizeof(int));

    int tb = 256;
    init_defaults_kernel<<<(N + tb - 1) / tb, tb>>>(grid_out, batch_out,
                                                    counts_out, N);
    compute_keys_kernel<<<(N + tb - 1) / tb, tb>>>(grid_coord, batch, N);
    bpack_kernel<<<1, 256>>>(W);
    hist_pass1_kernel<<<NSCANBLK, SCAN_T>>>();
    scan_blocksums_kernel<<<1, 1024>>>();
    hist_pass3_kernel<<<NSCANBLK, SCAN_T>>>(grid_out, batch_out, counts_out);
    scatter_pidx_kernel<<<(N + tb - 1) / tb, tb>>>(cluster_out, N);
    coord_mean_kernel<<<(N + tb - 1) / tb, tb>>>(coord, counts_out, coord_out, N);

    static int smem_set = 0;
    if (!smem_set) {
        cudaFuncSetAttribute(gemm_kernel,
                             cudaFuncAttributeMaxDynamicSharedMemorySize,
                             GEMM_SMEM);
        smem_set = 1;
    }
    gemm_kernel<<<(N + 127) / 128, 256, GEMM_SMEM>>>(bias, feat, counts_out,
                                                     feat_out, N);
}

// round 4
// speedup vs baseline: 1.7123x; 1.3047x over previous
#include <cuda_runtime.h>
#include <cuda_bf16.h>
#include <cstdint>

// ---------------------------------------------------------------------------
// GridPooling, 4-kernel pipeline:
//  K1: keys (byte-hist atomic) + W bf16 hi/lo pack
//  K2: single-pass decoupled-lookback scan over 8.4M-cell byte histogram
//      -> rank, CSR starts, unique decode (grid/batch/counts)
//  K3: scatter point ids into CSR lists + coord atomic sums + cluster out
//  K4: HMMA bf16 hi/lo GEMM (ldmatrix) w/ fused gather-mean, bias, coord div,
//      padded-row defaults
// ---------------------------------------------------------------------------

#define MAXN     1000000
#define HSIZE    (4 * 128 * 128 * 128)     // 8,388,608 byte cells
#define HWORDS   (HSIZE / 4)
#define NSCANBLK 2048
#define SCAN_T   512

typedef unsigned long long ull;

__device__ uint32_t g_histb[HWORDS + 2 * NSCANBLK];  // byte hist + lookback state
__device__ int      g_keys[MAXN];
__device__ int      g_rank[HSIZE];
__device__ int      g_start[MAXN];
__device__ int      g_cursor[MAXN];
__device__ int      g_pidx[MAXN];
__device__ int      g_U[1];
__device__ uint4    g_Bpack4[2304];   // B_hi words [n*36+kp], B_lo at +4608 words

// ---------------- K1: keys + bpack ----------------

__global__ void keys_bpack_kernel(const int* __restrict__ grid_coord,
                                  const int* __restrict__ batch,
                                  const float* __restrict__ Wg, int N) {
    if (blockIdx.x == gridDim.x - 1) {  // bpack block
        uint32_t* bp = reinterpret_cast<uint32_t*>(g_Bpack4);
        int tid = threadIdx.x;
#pragma unroll
        for (int q = 0; q < 16; q++) {
            int cell = q * 256 + tid;      // n in [0,128), kp in [0,32)
            int n = cell >> 5;
            int kp = cell & 31;
            float w0 = Wg[(2 * kp) * 128 + n];
            float w1 = Wg[(2 * kp + 1) * 128 + n];
            __nv_bfloat16 h0 = __float2bfloat16(w0), h1 = __float2bfloat16(w1);
            __nv_bfloat16 l0 = __float2bfloat16(w0 - __bfloat162float(h0));
            __nv_bfloat16 l1 = __float2bfloat16(w1 - __bfloat162float(h1));
            bp[n * 36 + kp] =
                ((uint32_t)__bfloat16_as_ushort(h1) << 16) | __bfloat16_as_ushort(h0);
            bp[4608 + n * 36 + kp] =
                ((uint32_t)__bfloat16_as_ushort(l1) << 16) | __bfloat16_as_ushort(l0);
        }
        return;
    }
    int i = blockIdx.x * 256 + threadIdx.x;
    if (i < N) {
        int gx = grid_coord[3 * i + 0] >> 1;
        int gy = grid_coord[3 * i + 1] >> 1;
        int gz = grid_coord[3 * i + 2] >> 1;
        int key = (batch[i] << 21) | (gx << 14) | (gy << 7) | gz;
        g_keys[i] = key;
        atomicAdd(&g_histb[key >> 2], 1u << ((key & 3) * 8));
    }
}

// ---------------- K2: decoupled-lookback scan ----------------
// per thread: 8 byte-cells. scan value packed (occ<<32)|cnt (each <= 1e6).

#define FLAGA (1ull << 62)
#define FLAGI (2ull << 62)
#define VMASK ((1ull << 62) - 1)

__device__ __forceinline__ ull warp_reduce_add(ull v) {
#pragma unroll
    for (int off = 16; off; off >>= 1)
        v += __shfl_down_sync(0xffffffffu, v, off);
    return __shfl_sync(0xffffffffu, v, 0);
}

__global__ __launch_bounds__(SCAN_T) void scan_kernel(float* __restrict__ grid_out,
                                                      float* __restrict__ batch_out,
                                                      float* __restrict__ counts_out) {
    __shared__ ull warp_tot[16];
    __shared__ ull sh_prefix;
    int tid = threadIdx.x, bid = blockIdx.x;
    int lane = tid & 31, wid = tid >> 5;

    const ull* h8 = reinterpret_cast<const ull*>(g_histb);
    ull h = h8[(size_t)bid * SCAN_T + tid];
    unsigned cbytes[8];
    int occ = 0, cnt = 0;
#pragma unroll
    for (int j = 0; j < 8; j++) {
        unsigned c = (unsigned)(h >> (8 * j)) & 0xFFu;
        cbytes[j] = c;
        occ += (c != 0);
        cnt += c;
    }
    ull v = ((ull)occ << 32) | (unsigned)cnt;

    // block scan
    ull incl = v;
#pragma unroll
    for (int off = 1; off < 32; off <<= 1) {
        ull n = __shfl_up_sync(0xffffffffu, incl, off);
        if (lane >= off) incl += n;
    }
    if (lane == 31) warp_tot[wid] = incl;
    __syncthreads();
    if (wid == 0) {
        ull w = (lane < 16) ? warp_tot[lane] : 0ull;
#pragma unroll
        for (int off = 1; off < 16; off <<= 1) {
            ull n = __shfl_up_sync(0xffffffffu, w, off);
            if (lane >= off) w += n;
        }
        if (lane < 16) warp_tot[lane] = w;
    }
    __syncthreads();
    ull excl_local = ((wid > 0) ? warp_tot[wid - 1] : 0ull) + incl - v;
    ull total = warp_tot[15];

    ull* state = reinterpret_cast<ull*>(g_histb + HWORDS);
    if (tid == 0) {
        if (bid == 0) {
            atomicExch(&state[0], FLAGI | total);
            sh_prefix = 0ull;
        } else {
            atomicExch(&state[bid], FLAGA | total);
        }
    }
    if (bid > 0 && wid == 0) {
        ull excl = 0;
        int idx = bid - 1;
        while (true) {
            int look = idx - lane;
            ull s = (look >= 0) ? atomicAdd(&state[look], 0ull) : FLAGI;
            unsigned f = (unsigned)(s >> 62);
            unsigned incm = __ballot_sync(0xffffffffu, f == 2u);
            unsigned zm = __ballot_sync(0xffffffffu, f == 0u);
            if (incm) {
                int fi = __ffs(incm) - 1;
                unsigned below = (fi == 0) ? 0u : ((1u << fi) - 1u);
                if (zm & below) continue;  // a nearer block not ready yet
                ull contrib = (lane <= fi) ? (s & VMASK) : 0ull;
                excl += warp_reduce_add(contrib);
                break;
            } else {
                if (zm) continue;
                excl += warp_reduce_add(s & VMASK);
                idx -= 32;
            }
        }
        if (lane == 0) {
            atomicExch(&state[bid], FLAGI | (excl + total));
            sh_prefix = excl;
        }
    }
    __syncthreads();
    ull prefix = sh_prefix;
    if (bid == NSCANBLK - 1 && tid == 0)
        g_U[0] = (int)((prefix + total) >> 32);

    int r = (int)((prefix >> 32) + (excl_local >> 32));
    int o = (int)((prefix & 0xFFFFFFFFull) + (excl_local & 0xFFFFFFFFull));
    int key0 = bid * (SCAN_T * 8) + tid * 8;
#pragma unroll
    for (int j = 0; j < 8; j++) {
        unsigned c = cbytes[j];
        if (c) {
            int key = key0 + j;
            g_rank[key] = r;
            g_start[r] = o;
            g_cursor[r] = o;
            grid_out[3 * r + 0] = (float)((key >> 14) & 127);
            grid_out[3 * r + 1] = (float)((key >> 7) & 127);
            grid_out[3 * r + 2] = (float)(key & 127);
            batch_out[r] = (float)(key >> 21);
            counts_out[r] = (float)c;
            r++;
            o += (int)c;
        }
    }
}

// ---------------- K3: scatter ----------------

__global__ void scatter_kernel(const float* __restrict__ coord,
                               float* __restrict__ coord_out,
                               float* __restrict__ cluster_out, int N) {
    int i = blockIdx.x * blockDim.x + threadIdx.x;
    if (i < N) {
        int c = g_rank[g_keys[i]];
        int pos = atomicAdd(&g_cursor[c], 1);
        g_pidx[pos] = i;
        cluster_out[i] = (float)c;
        atomicAdd(&coord_out[3 * c + 0], coord[3 * i + 0]);
        atomicAdd(&coord_out[3 * c + 1], coord[3 * i + 1]);
        atomicAdd(&coord_out[3 * c + 2], coord[3 * i + 2]);
    }
}

// ---------------- K4: HMMA GEMM ----------------
// smem words: A_hi 0, A_lo 4608, B_hi 9216, B_lo 13824 (stride 36 words/row)

#define GEMM_SMEM 73728

__device__ __forceinline__ void mma_bf16(float* c, const uint32_t* a,
                                         uint32_t b0, uint32_t b1) {
    asm volatile(
        "mma.sync.aligned.m16n8k16.row.col.f32.bf16.bf16.f32 "
        "{%0,%1,%2,%3}, {%4,%5,%6,%7}, {%8,%9}, {%0,%1,%2,%3};"
        : "+f"(c[0]), "+f"(c[1]), "+f"(c[2]), "+f"(c[3])
        : "r"(a[0]), "r"(a[1]), "r"(a[2]), "r"(a[3]), "r"(b0), "r"(b1));
}

__device__ __forceinline__ void ldsm4(uint32_t* r, uint32_t addr) {
    asm volatile(
        "ldmatrix.sync.aligned.m8n8.x4.shared.b16 {%0,%1,%2,%3}, [%4];"
        : "=r"(r[0]), "=r"(r[1]), "=r"(r[2]), "=r"(r[3]) : "r"(addr));
}

__device__ __forceinline__ uint32_t smem_u32(const void* p) {
    uint32_t a;
    asm("{ .reg .u64 t; cvta.to.shared.u64 t, %1; cvt.u32.u64 %0, t; }"
        : "=r"(a) : "l"(p));
    return a;
}

__global__ __launch_bounds__(256, 2) void gemm_kernel(
    const float* __restrict__ bias, const float* __restrict__ feat,
    float* __restrict__ counts_out, float* __restrict__ coord_out,
    float* __restrict__ grid_out, float* __restrict__ batch_out,
    float* __restrict__ out, int N) {
    extern __shared__ uint32_t sm[];
    int tid = threadIdx.x;
    int rb = blockIdx.x * 128;
    int U = g_U[0];

    if (rb >= U) {  // pure padding tile
#pragma unroll
        for (int q = 0; q < 16; q++) {
            int t = q * 256 + tid;
            int row = rb + (t >> 5);
            if (row < N)
                reinterpret_cast<float4*>(out + (size_t)row * 128)[t & 31] =
                    make_float4(0.f, 0.f, 0.f, 0.f);
        }
        if (tid < 128) {
            int gr = rb + tid;
            if (gr < N) {
                batch_out[gr] = -1.0f;
                grid_out[3 * gr + 0] = 127.0f;
                grid_out[3 * gr + 1] = 127.0f;
                grid_out[3 * gr + 2] = 127.0f;
                counts_out[gr] = 0.0f;
            }
        }
        return;
    }

    // B tiles (L2-resident coalesced copy)
    {
        uint4* dst = reinterpret_cast<uint4*>(sm + 9216);
#pragma unroll
        for (int q = 0; q < 9; q++) dst[q * 256 + tid] = g_Bpack4[q * 256 + tid];
    }

    // A: gather-mean; thread = (row, half of 64 ch)
    {
        int row = tid >> 1;
        int half = tid & 1;
        int gr = rb + row;
        float acc[32];
#pragma unroll
        for (int q = 0; q < 32; q++) acc[q] = 0.f;
        float inv = 0.f;
        if (gr < U) {
            int s = g_start[gr];
            int c = (int)counts_out[gr];
            inv = 1.0f / (float)c;
            for (int j = 0; j < c; j++) {
                int p = g_pidx[s + j];
                const float4* f =
                    reinterpret_cast<const float4*>(feat + (size_t)p * 64 + half * 32);
#pragma unroll
                for (int q = 0; q < 8; q++) {
                    float4 vv = f[q];
                    acc[4 * q + 0] += vv.x;
                    acc[4 * q + 1] += vv.y;
                    acc[4 * q + 2] += vv.z;
                    acc[4 * q + 3] += vv.w;
                }
            }
        }
        int base = row * 36 + half * 16;
#pragma unroll
        for (int c2 = 0; c2 < 16; c2++) {
            float x0 = acc[2 * c2] * inv, x1 = acc[2 * c2 + 1] * inv;
            __nv_bfloat16 h0 = __float2bfloat16(x0), h1 = __float2bfloat16(x1);
            __nv_bfloat16 l0 = __float2bfloat16(x0 - __bfloat162float(h0));
            __nv_bfloat16 l1 = __float2bfloat16(x1 - __bfloat162float(h1));
            sm[base + c2] = ((uint32_t)__bfloat16_as_ushort(h1) << 16) |
                            __bfloat16_as_ushort(h0);
            sm[4608 + base + c2] = ((uint32_t)__bfloat16_as_ushort(l1) << 16) |
                                   __bfloat16_as_ushort(l0);
        }
    }
    __syncthreads();

    int wid = tid >> 5, lane = tid & 31;
    int g = lane >> 2, tig = lane & 3;
    int wm = wid & 3, wn = wid >> 2;

    uint32_t smb = smem_u32(sm);
    int lrow = lane & 15, khalf = lane >> 4;
    uint32_t aAddr0 = smb + 4u * ((wm * 32 + lrow) * 36 + khalf * 4);
    uint32_t aAddr1 = aAddr0 + 2304u;                    // +16 rows
    uint32_t bAddr = smb + 36864u + 4u * ((wn * 64 + lrow) * 36 + khalf * 4);

    float c[2][8][4];
#pragma unroll
    for (int mt = 0; mt < 2; mt++)
#pragma unroll
        for (int j = 0; j < 8; j++)
#pragma unroll
            for (int q = 0; q < 4; q++) c[mt][j][q] = 0.f;

#pragma unroll
    for (int ks = 0; ks < 4; ks++) {
        uint32_t off = ks * 32u;
        uint32_t ah0[4], ah1[4], al0[4], al1[4];
        ldsm4(ah0, aAddr0 + off);
        ldsm4(ah1, aAddr1 + off);
        ldsm4(al0, aAddr0 + 18432u + off);
        ldsm4(al1, aAddr1 + 18432u + off);
#pragma unroll
        for (int j2 = 0; j2 < 4; j2++) {
            uint32_t bh[4], bl[4];
            ldsm4(bh, bAddr + j2 * 2304u + off);
            mma_bf16(c[0][2 * j2],     ah0, bh[0], bh[2]);
            mma_bf16(c[0][2 * j2 + 1], ah0, bh[1], bh[3]);
            mma_bf16(c[1][2 * j2],     ah1, bh[0], bh[2]);
            mma_bf16(c[1][2 * j2 + 1], ah1, bh[1], bh[3]);
            mma_bf16(c[0][2 * j2],     al0, bh[0], bh[2]);
            mma_bf16(c[0][2 * j2 + 1], al0, bh[1], bh[3]);
            mma_bf16(c[1][2 * j2],     al1, bh[0], bh[2]);
            mma_bf16(c[1][2 * j2 + 1], al1, bh[1], bh[3]);
            ldsm4(bl, bAddr + 18432u + j2 * 2304u + off);
            mma_bf16(c[0][2 * j2],     ah0, bl[0], bl[2]);
            mma_bf16(c[0][2 * j2 + 1], ah0, bl[1], bl[3]);
            mma_bf16(c[1][2 * j2],     ah1, bl[0], bl[2]);
            mma_bf16(c[1][2 * j2 + 1], ah1, bl[1], bl[3]);
        }
    }

    // epilogue: +bias (gated), direct stores
#pragma unroll
    for (int mt = 0; mt < 2; mt++) {
#pragma unroll
        for (int half = 0; half < 2; half++) {
            int gr = rb + wm * 32 + mt * 16 + g + half * 8;
            if (gr >= N) continue;
            bool on = gr < U;
#pragma unroll
            for (int j = 0; j < 8; j++) {
                int col = wn * 64 + j * 8 + tig * 2;
                float2 v;
                if (on) {
                    float2 bv = *reinterpret_cast<const float2*>(bias + col);
                    v.x = c[mt][j][half * 2 + 0] + bv.x;
                    v.y = c[mt][j][half * 2 + 1] + bv.y;
                } else {
                    v = make_float2(0.f, 0.f);
                }
                *reinterpret_cast<float2*>(out + (size_t)gr * 128 + col) = v;
            }
        }
    }

    // coord divide + padded-row defaults
    if (tid < 128) {
        int gr = rb + tid;
        if (gr < N) {
            if (gr < U) {
                float cnt = counts_out[gr];
                if (cnt > 1.5f) {
                    float inv = 1.0f / cnt;
                    coord_out[3 * gr + 0] *= inv;
                    coord_out[3 * gr + 1] *= inv;
                    coord_out[3 * gr + 2] *= inv;
                }
            } else {
                batch_out[gr] = -1.0f;
                grid_out[3 * gr + 0] = 127.0f;
                grid_out[3 * gr + 1] = 127.0f;
                grid_out[3 * gr + 2] = 127.0f;
                counts_out[gr] = 0.0f;
            }
        }
    }
}

// ---------------- launch ----------------

extern "C" void kernel_launch(void* const* d_in, const int* in_sizes, int n_in,
                              void* d_out, int out_size) {
    const float* feat       = (const float*)d_in[0];
    const float* coord      = (const float*)d_in[1];
    const int*   grid_coord = (const int*)d_in[2];
    const int*   batch      = (const int*)d_in[3];
    const float* W          = (const float*)d_in[4];
    const float* bias       = (const float*)d_in[5];
    int N = in_sizes[3];
    if (N > MAXN) N = MAXN;

    float* out         = (float*)d_out;
    float* feat_out    = out;
    float* coord_out   = out + (size_t)N * 128;
    float* grid_out    = coord_out + (size_t)N * 3;
    float* batch_out   = grid_out + (size_t)N * 3;
    float* cluster_out = batch_out + N;
    float* counts_out  = cluster_out + N;

    void* p_hist;
    cudaGetSymbolAddress(&p_hist, g_histb);
    cudaMemsetAsync(p_hist, 0, (size_t)(HWORDS + 2 * NSCANBLK) * 4);
    cudaMemsetAsync(coord_out, 0, (size_t)N * 3 * sizeof(float));

    int nb = (N + 255) / 256;
    keys_bpack_kernel<<<nb + 1, 256>>>(grid_coord, batch, W, N);
    scan_kernel<<<NSCANBLK, SCAN_T>>>(grid_out, batch_out, counts_out);
    scatter_kernel<<<nb, 256>>>(coord, coord_out, cluster_out, N);

    static int smem_set = 0;
    if (!smem_set) {
        cudaFuncSetAttribute(gemm_kernel,
                             cudaFuncAttributeMaxDynamicSharedMemorySize,
                             GEMM_SMEM);
        smem_set = 1;
    }
    gemm_kernel<<<(N + 127) / 128, 256, GEMM_SMEM>>>(
        bias, feat, counts_out, coord_out, grid_out, batch_out, feat_out, N);
}

// round 5
// speedup vs baseline: 1.7980x; 1.0501x over previous
#include <cuda_runtime.h>
#include <cuda_bf16.h>
#include <cstdint>

// ---------------------------------------------------------------------------
// GridPooling, 4-kernel pipeline:
//  K1: keys (byte-hist atomic) + W bf16 hi/lo pack
//  K2: single-pass decoupled-lookback scan over 8.4M-cell byte histogram
//  K3: scatter point ids into CSR lists + coord atomic sums + cluster out
//  K4: HMMA bf16 hi/lo GEMM, 512 thr / 32x32 warp tiles for 50% occupancy
// ---------------------------------------------------------------------------

#define MAXN     1000000
#define HSIZE    (4 * 128 * 128 * 128)     // 8,388,608 byte cells
#define HWORDS   (HSIZE / 4)
#define NSCANBLK 2048
#define SCAN_T   512

typedef unsigned long long ull;

__device__ uint32_t g_histb[HWORDS + 2 * NSCANBLK];  // byte hist + lookback state
__device__ int      g_keys[MAXN];
__device__ int      g_rank[HSIZE];
__device__ int      g_start[MAXN];
__device__ int      g_cursor[MAXN];
__device__ int      g_pidx[MAXN];
__device__ int      g_U[1];
__device__ uint4    g_Bpack4[2304];   // B_hi words [n*36+kp], B_lo at +4608 words

// ---------------- K1: keys + bpack ----------------

__global__ void keys_bpack_kernel(const int* __restrict__ grid_coord,
                                  const int* __restrict__ batch,
                                  const float* __restrict__ Wg, int N) {
    if (blockIdx.x == gridDim.x - 1) {  // bpack block
        uint32_t* bp = reinterpret_cast<uint32_t*>(g_Bpack4);
        int tid = threadIdx.x;
#pragma unroll
        for (int q = 0; q < 16; q++) {
            int cell = q * 256 + tid;      // n in [0,128), kp in [0,32)
            int n = cell >> 5;
            int kp = cell & 31;
            float w0 = Wg[(2 * kp) * 128 + n];
            float w1 = Wg[(2 * kp + 1) * 128 + n];
            __nv_bfloat16 h0 = __float2bfloat16(w0), h1 = __float2bfloat16(w1);
            __nv_bfloat16 l0 = __float2bfloat16(w0 - __bfloat162float(h0));
            __nv_bfloat16 l1 = __float2bfloat16(w1 - __bfloat162float(h1));
            bp[n * 36 + kp] =
                ((uint32_t)__bfloat16_as_ushort(h1) << 16) | __bfloat16_as_ushort(h0);
            bp[4608 + n * 36 + kp] =
                ((uint32_t)__bfloat16_as_ushort(l1) << 16) | __bfloat16_as_ushort(l0);
        }
        return;
    }
    int i = blockIdx.x * 256 + threadIdx.x;
    if (i < N) {
        int gx = grid_coord[3 * i + 0] >> 1;
        int gy = grid_coord[3 * i + 1] >> 1;
        int gz = grid_coord[3 * i + 2] >> 1;
        int key = (batch[i] << 21) | (gx << 14) | (gy << 7) | gz;
        g_keys[i] = key;
        atomicAdd(&g_histb[key >> 2], 1u << ((key & 3) * 8));
    }
}

// ---------------- K2: decoupled-lookback scan ----------------

#define FLAGA (1ull << 62)
#define FLAGI (2ull << 62)
#define VMASK ((1ull << 62) - 1)

__device__ __forceinline__ ull warp_reduce_add(ull v) {
#pragma unroll
    for (int off = 16; off; off >>= 1)
        v += __shfl_down_sync(0xffffffffu, v, off);
    return __shfl_sync(0xffffffffu, v, 0);
}

__global__ __launch_bounds__(SCAN_T) void scan_kernel(float* __restrict__ grid_out,
                                                      float* __restrict__ batch_out,
                                                      float* __restrict__ counts_out) {
    __shared__ ull warp_tot[16];
    __shared__ ull sh_prefix;
    int tid = threadIdx.x, bid = blockIdx.x;
    int lane = tid & 31, wid = tid >> 5;

    const ull* h8 = reinterpret_cast<const ull*>(g_histb);
    ull h = h8[(size_t)bid * SCAN_T + tid];
    unsigned cbytes[8];
    int occ = 0, cnt = 0;
#pragma unroll
    for (int j = 0; j < 8; j++) {
        unsigned c = (unsigned)(h >> (8 * j)) & 0xFFu;
        cbytes[j] = c;
        occ += (c != 0);
        cnt += c;
    }
    ull v = ((ull)occ << 32) | (unsigned)cnt;

    ull incl = v;
#pragma unroll
    for (int off = 1; off < 32; off <<= 1) {
        ull n = __shfl_up_sync(0xffffffffu, incl, off);
        if (lane >= off) incl += n;
    }
    if (lane == 31) warp_tot[wid] = incl;
    __syncthreads();
    if (wid == 0) {
        ull w = (lane < 16) ? warp_tot[lane] : 0ull;
#pragma unroll
        for (int off = 1; off < 16; off <<= 1) {
            ull n = __shfl_up_sync(0xffffffffu, w, off);
            if (lane >= off) w += n;
        }
        if (lane < 16) warp_tot[lane] = w;
    }
    __syncthreads();
    ull excl_local = ((wid > 0) ? warp_tot[wid - 1] : 0ull) + incl - v;
    ull total = warp_tot[15];

    ull* state = reinterpret_cast<ull*>(g_histb + HWORDS);
    if (tid == 0) {
        if (bid == 0) {
            atomicExch(&state[0], FLAGI | total);
            sh_prefix = 0ull;
        } else {
            atomicExch(&state[bid], FLAGA | total);
        }
    }
    if (bid > 0 && wid == 0) {
        ull excl = 0;
        int idx = bid - 1;
        while (true) {
            int look = idx - lane;
            ull s = (look >= 0) ? atomicAdd(&state[look], 0ull) : FLAGI;
            unsigned f = (unsigned)(s >> 62);
            unsigned incm = __ballot_sync(0xffffffffu, f == 2u);
            unsigned zm = __ballot_sync(0xffffffffu, f == 0u);
            if (incm) {
                int fi = __ffs(incm) - 1;
                unsigned below = (fi == 0) ? 0u : ((1u << fi) - 1u);
                if (zm & below) continue;
                ull contrib = (lane <= fi) ? (s & VMASK) : 0ull;
                excl += warp_reduce_add(contrib);
                break;
            } else {
                if (zm) continue;
                excl += warp_reduce_add(s & VMASK);
                idx -= 32;
            }
        }
        if (lane == 0) {
            atomicExch(&state[bid], FLAGI | (excl + total));
            sh_prefix = excl;
        }
    }
    __syncthreads();
    ull prefix = sh_prefix;
    if (bid == NSCANBLK - 1 && tid == 0)
        g_U[0] = (int)((prefix + total) >> 32);

    int r = (int)((prefix >> 32) + (excl_local >> 32));
    int o = (int)((prefix & 0xFFFFFFFFull) + (excl_local & 0xFFFFFFFFull));
    int key0 = bid * (SCAN_T * 8) + tid * 8;
#pragma unroll
    for (int j = 0; j < 8; j++) {
        unsigned c = cbytes[j];
        if (c) {
            int key = key0 + j;
            g_rank[key] = r;
            g_start[r] = o;
            g_cursor[r] = o;
            grid_out[3 * r + 0] = (float)((key >> 14) & 127);
            grid_out[3 * r + 1] = (float)((key >> 7) & 127);
            grid_out[3 * r + 2] = (float)(key & 127);
            batch_out[r] = (float)(key >> 21);
            counts_out[r] = (float)c;
            r++;
            o += (int)c;
        }
    }
}

// ---------------- K3: scatter ----------------

__global__ void scatter_kernel(const float* __restrict__ coord,
                               float* __restrict__ coord_out,
                               float* __restrict__ cluster_out, int N) {
    int i = blockIdx.x * blockDim.x + threadIdx.x;
    if (i < N) {
        int c = g_rank[g_keys[i]];
        int pos = atomicAdd(&g_cursor[c], 1);
        g_pidx[pos] = i;
        cluster_out[i] = (float)c;
        atomicAdd(&coord_out[3 * c + 0], coord[3 * i + 0]);
        atomicAdd(&coord_out[3 * c + 1], coord[3 * i + 1]);
        atomicAdd(&coord_out[3 * c + 2], coord[3 * i + 2]);
    }
}

// ---------------- K4: HMMA GEMM, 512 threads ----------------
// smem words: A_hi 0, A_lo 4608, B_hi 9216, B_lo 13824 (stride 36 words/row)

#define GEMM_SMEM 73728

__device__ __forceinline__ void mma_bf16(float* c, const uint32_t* a,
                                         uint32_t b0, uint32_t b1) {
    asm volatile(
        "mma.sync.aligned.m16n8k16.row.col.f32.bf16.bf16.f32 "
        "{%0,%1,%2,%3}, {%4,%5,%6,%7}, {%8,%9}, {%0,%1,%2,%3};"
        : "+f"(c[0]), "+f"(c[1]), "+f"(c[2]), "+f"(c[3])
        : "r"(a[0]), "r"(a[1]), "r"(a[2]), "r"(a[3]), "r"(b0), "r"(b1));
}

__device__ __forceinline__ void ldsm4(uint32_t* r, uint32_t addr) {
    asm volatile(
        "ldmatrix.sync.aligned.m8n8.x4.shared.b16 {%0,%1,%2,%3}, [%4];"
        : "=r"(r[0]), "=r"(r[1]), "=r"(r[2]), "=r"(r[3]) : "r"(addr));
}

__device__ __forceinline__ uint32_t smem_u32(const void* p) {
    uint32_t a;
    asm("{ .reg .u64 t; cvta.to.shared.u64 t, %1; cvt.u32.u64 %0, t; }"
        : "=r"(a) : "l"(p));
    return a;
}

__global__ __launch_bounds__(512, 2) void gemm_kernel(
    const float* __restrict__ bias, const float* __restrict__ feat,
    float* __restrict__ counts_out, float* __restrict__ coord_out,
    float* __restrict__ grid_out, float* __restrict__ batch_out,
    float* __restrict__ out, int N) {
    extern __shared__ uint32_t sm[];
    int tid = threadIdx.x;
    int rb = blockIdx.x * 128;
    int U = g_U[0];

    if (rb >= U) {  // pure padding tile
#pragma unroll
        for (int q = 0; q < 4; q++) {
            int t = q * 512 + tid;
            int row = rb + (t >> 4);
            if (row < N)
                reinterpret_cast<float4*>(out + (size_t)row * 128)[t & 15] =
                    make_float4(0.f, 0.f, 0.f, 0.f);
        }
        if (tid < 128) {
            int gr = rb + tid;
            if (gr < N) {
                batch_out[gr] = -1.0f;
                grid_out[3 * gr + 0] = 127.0f;
                grid_out[3 * gr + 1] = 127.0f;
                grid_out[3 * gr + 2] = 127.0f;
                counts_out[gr] = 0.0f;
            }
        }
        return;
    }

    // B tiles (L2-resident coalesced copy): 2304 uint4
    {
        uint4* dst = reinterpret_cast<uint4*>(sm + 9216);
#pragma unroll
        for (int q = 0; q < 5; q++) {
            int idx = q * 512 + tid;
            if (idx < 2304) dst[idx] = g_Bpack4[idx];
        }
    }

    // A: gather-mean; thread = (row, quarter of 64 ch) -> 16 ch each
    {
        int row = tid >> 2;
        int quarter = tid & 3;
        int gr = rb + row;
        float acc[16];
#pragma unroll
        for (int q = 0; q < 16; q++) acc[q] = 0.f;
        float inv = 0.f;
        if (gr < U) {
            int s = g_start[gr];
            int c = (int)counts_out[gr];
            inv = 1.0f / (float)c;
            for (int j = 0; j < c; j++) {
                int p = g_pidx[s + j];
                const float4* f =
                    reinterpret_cast<const float4*>(feat + (size_t)p * 64 + quarter * 16);
#pragma unroll
                for (int q = 0; q < 4; q++) {
                    float4 vv = f[q];
                    acc[4 * q + 0] += vv.x;
                    acc[4 * q + 1] += vv.y;
                    acc[4 * q + 2] += vv.z;
                    acc[4 * q + 3] += vv.w;
                }
            }
        }
        int base = row * 36 + quarter * 8;
#pragma unroll
        for (int c2 = 0; c2 < 8; c2++) {
            float x0 = acc[2 * c2] * inv, x1 = acc[2 * c2 + 1] * inv;
            __nv_bfloat16 h0 = __float2bfloat16(x0), h1 = __float2bfloat16(x1);
            __nv_bfloat16 l0 = __float2bfloat16(x0 - __bfloat162float(h0));
            __nv_bfloat16 l1 = __float2bfloat16(x1 - __bfloat162float(h1));
            sm[base + c2] = ((uint32_t)__bfloat16_as_ushort(h1) << 16) |
                            __bfloat16_as_ushort(h0);
            sm[4608 + base + c2] = ((uint32_t)__bfloat16_as_ushort(l1) << 16) |
                                   __bfloat16_as_ushort(l0);
        }
    }
    __syncthreads();

    // 16 warps: 4 along M (32 rows) x 4 along N (32 cols)
    int wid = tid >> 5, lane = tid & 31;
    int g = lane >> 2, tig = lane & 3;
    int wm = wid & 3, wn = wid >> 2;

    uint32_t smb = smem_u32(sm);
    int lrow = lane & 15, khalf = lane >> 4;
    uint32_t aAddr = smb + 4u * ((wm * 32 + lrow) * 36 + khalf * 4);
    uint32_t bAddr = smb + 36864u + 4u * ((wn * 32 + lrow) * 36 + khalf * 4);

    float c[2][4][4];
#pragma unroll
    for (int mt = 0; mt < 2; mt++)
#pragma unroll
        for (int nt = 0; nt < 4; nt++)
#pragma unroll
            for (int q = 0; q < 4; q++) c[mt][nt][q] = 0.f;

#pragma unroll
    for (int ks = 0; ks < 4; ks++) {
        uint32_t off = ks * 32u;
        uint32_t ah0[4], ah1[4], al0[4], al1[4];
        ldsm4(ah0, aAddr + off);
        ldsm4(ah1, aAddr + 2304u + off);
        ldsm4(al0, aAddr + 18432u + off);
        ldsm4(al1, aAddr + 18432u + 2304u + off);
        uint32_t bh0[4], bh1[4], bl0[4], bl1[4];
        ldsm4(bh0, bAddr + off);
        ldsm4(bh1, bAddr + 2304u + off);
        ldsm4(bl0, bAddr + 18432u + off);
        ldsm4(bl1, bAddr + 18432u + 2304u + off);
#pragma unroll
        for (int nt = 0; nt < 4; nt++) {
            uint32_t b0h = (nt < 2 ? bh0 : bh1)[nt & 1];
            uint32_t b1h = (nt < 2 ? bh0 : bh1)[2 + (nt & 1)];
            mma_bf16(c[0][nt], ah0, b0h, b1h);
            mma_bf16(c[1][nt], ah1, b0h, b1h);
            mma_bf16(c[0][nt], al0, b0h, b1h);
            mma_bf16(c[1][nt], al1, b0h, b1h);
            uint32_t b0l = (nt < 2 ? bl0 : bl1)[nt & 1];
            uint32_t b1l = (nt < 2 ? bl0 : bl1)[2 + (nt & 1)];
            mma_bf16(c[0][nt], ah0, b0l, b1l);
            mma_bf16(c[1][nt], ah1, b0l, b1l);
        }
    }

    // epilogue: +bias (gated), direct stores
#pragma unroll
    for (int mt = 0; mt < 2; mt++) {
#pragma unroll
        for (int half = 0; half < 2; half++) {
            int gr = rb + wm * 32 + mt * 16 + g + half * 8;
            if (gr >= N) continue;
            bool on = gr < U;
#pragma unroll
            for (int nt = 0; nt < 4; nt++) {
                int col = wn * 32 + nt * 8 + tig * 2;
                float2 v;
                if (on) {
                    float2 bv = *reinterpret_cast<const float2*>(bias + col);
                    v.x = c[mt][nt][half * 2 + 0] + bv.x;
                    v.y = c[mt][nt][half * 2 + 1] + bv.y;
                } else {
                    v = make_float2(0.f, 0.f);
                }
                *reinterpret_cast<float2*>(out + (size_t)gr * 128 + col) = v;
            }
        }
    }

    // coord divide + padded-row defaults
    if (tid < 128) {
        int gr = rb + tid;
        if (gr < N) {
            if (gr < U) {
                float cnt = counts_out[gr];
                if (cnt > 1.5f) {
                    float inv = 1.0f / cnt;
                    coord_out[3 * gr + 0] *= inv;
                    coord_out[3 * gr + 1] *= inv;
                    coord_out[3 * gr + 2] *= inv;
                }
            } else {
                batch_out[gr] = -1.0f;
                grid_out[3 * gr + 0] = 127.0f;
                grid_out[3 * gr + 1] = 127.0f;
                grid_out[3 * gr + 2] = 127.0f;
                counts_out[gr] = 0.0f;
            }
        }
    }
}

// ---------------- launch ----------------

extern "C" void kernel_launch(void* const* d_in, const int* in_sizes, int n_in,
                              void* d_out, int out_size) {
    const float* feat       = (const float*)d_in[0];
    const float* coord      = (const float*)d_in[1];
    const int*   grid_coord = (const int*)d_in[2];
    const int*   batch      = (const int*)d_in[3];
    const float* W          = (const float*)d_in[4];
    const float* bias       = (const float*)d_in[5];
    int N = in_sizes[3];
    if (N > MAXN) N = MAXN;

    float* out         = (float*)d_out;
    float* feat_out    = out;
    float* coord_out   = out + (size_t)N * 128;
    float* grid_out    = coord_out + (size_t)N * 3;
    float* batch_out   = grid_out + (size_t)N * 3;
    float* cluster_out = batch_out + N;
    float* counts_out  = cluster_out + N;

    void* p_hist;
    cudaGetSymbolAddress(&p_hist, g_histb);
    cudaMemsetAsync(p_hist, 0, (size_t)(HWORDS + 2 * NSCANBLK) * 4);
    cudaMemsetAsync(coord_out, 0, (size_t)N * 3 * sizeof(float));

    int nb = (N + 255) / 256;
    keys_bpack_kernel<<<nb + 1, 256>>>(grid_coord, batch, W, N);
    scan_kernel<<<NSCANBLK, SCAN_T>>>(grid_out, batch_out, counts_out);
    scatter_kernel<<<nb, 256>>>(coord, coord_out, cluster_out, N);

    static int smem_set = 0;
    if (!smem_set) {
        cudaFuncSetAttribute(gemm_kernel,
                             cudaFuncAttributeMaxDynamicSharedMemorySize,
                             GEMM_SMEM);
        smem_set = 1;
    }
    gemm_kernel<<<(N + 127) / 128, 512, GEMM_SMEM>>>(
        bias, feat, counts_out, coord_out, grid_out, batch_out, feat_out, N);
}

// round 6
// speedup vs baseline: 1.9216x; 1.0688x over previous
#include <cuda_runtime.h>
#include <cuda_bf16.h>
#include <cstdint>

// ---------------------------------------------------------------------------
// GridPooling, 4-kernel pipeline:
//  K1: keys (byte-hist atomic) + W bf16 hi/lo pack (column-permuted)
//  K2: single-pass decoupled-lookback scan over 8.4M-cell byte histogram
//  K3: scatter point ids into CSR lists + coord atomic sums + cluster out
//  K4: HMMA bf16 hi/lo GEMM, 512 thr, permuted-B -> STG.128 epilogue
// ---------------------------------------------------------------------------

#define MAXN     1000000
#define HSIZE    (4 * 128 * 128 * 128)     // 8,388,608 byte cells
#define HWORDS   (HSIZE / 4)
#define NSCANBLK 2048
#define SCAN_T   512

typedef unsigned long long ull;

__device__ uint32_t g_histb[HWORDS + 2 * NSCANBLK];  // byte hist + lookback state
__device__ int      g_keys[MAXN];
__device__ int      g_rank[HSIZE];
__device__ int      g_start[MAXN];
__device__ int      g_cursor[MAXN];
__device__ int      g_pidx[MAXN];
__device__ int      g_U[1];
__device__ uint4    g_Bpack4[2304];   // B_hi words [n*36+kp], B_lo at +4608 words

// column permutation within each 32-col warp group:
// logical n_local = 16t + 4j + r  ->  phys tile (2t + (r>>1)), phys col 2j+(r&1)
__device__ __forceinline__ int col_perm(int n) {
    int nl = n & 31;
    int t = nl >> 4, r = nl & 3, j = (nl >> 2) & 3;
    return (n & ~31) | (((2 * t + (r >> 1)) << 3) + 2 * j + (r & 1));
}

// ---------------- K1: keys + bpack ----------------

__global__ void keys_bpack_kernel(const int* __restrict__ grid_coord,
                                  const int* __restrict__ batch,
                                  const float* __restrict__ Wg, int N) {
    if (blockIdx.x == gridDim.x - 1) {  // bpack block
        uint32_t* bp = reinterpret_cast<uint32_t*>(g_Bpack4);
        int tid = threadIdx.x;
#pragma unroll
        for (int q = 0; q < 16; q++) {
            int cell = q * 256 + tid;      // n in [0,128), kp in [0,32)
            int n = cell >> 5;
            int kp = cell & 31;
            float w0 = Wg[(2 * kp) * 128 + n];
            float w1 = Wg[(2 * kp + 1) * 128 + n];
            __nv_bfloat16 h0 = __float2bfloat16(w0), h1 = __float2bfloat16(w1);
            __nv_bfloat16 l0 = __float2bfloat16(w0 - __bfloat162float(h0));
            __nv_bfloat16 l1 = __float2bfloat16(w1 - __bfloat162float(h1));
            int np = col_perm(n);
            bp[np * 36 + kp] =
                ((uint32_t)__bfloat16_as_ushort(h1) << 16) | __bfloat16_as_ushort(h0);
            bp[4608 + np * 36 + kp] =
                ((uint32_t)__bfloat16_as_ushort(l1) << 16) | __bfloat16_as_ushort(l0);
        }
        return;
    }
    int i = blockIdx.x * 256 + threadIdx.x;
    if (i < N) {
        int gx = grid_coord[3 * i + 0] >> 1;
        int gy = grid_coord[3 * i + 1] >> 1;
        int gz = grid_coord[3 * i + 2] >> 1;
        int key = (batch[i] << 21) | (gx << 14) | (gy << 7) | gz;
        g_keys[i] = key;
        atomicAdd(&g_histb[key >> 2], 1u << ((key & 3) * 8));
    }
}

// ---------------- K2: decoupled-lookback scan ----------------

#define FLAGA (1ull << 62)
#define FLAGI (2ull << 62)
#define VMASK ((1ull << 62) - 1)

__device__ __forceinline__ ull warp_reduce_add(ull v) {
#pragma unroll
    for (int off = 16; off; off >>= 1)
        v += __shfl_down_sync(0xffffffffu, v, off);
    return __shfl_sync(0xffffffffu, v, 0);
}

__global__ __launch_bounds__(SCAN_T) void scan_kernel(float* __restrict__ grid_out,
                                                      float* __restrict__ batch_out,
                                                      float* __restrict__ counts_out) {
    __shared__ ull warp_tot[16];
    __shared__ ull sh_prefix;
    int tid = threadIdx.x, bid = blockIdx.x;
    int lane = tid & 31, wid = tid >> 5;

    const ull* h8 = reinterpret_cast<const ull*>(g_histb);
    ull h = h8[(size_t)bid * SCAN_T + tid];
    unsigned cbytes[8];
    int occ = 0, cnt = 0;
#pragma unroll
    for (int j = 0; j < 8; j++) {
        unsigned c = (unsigned)(h >> (8 * j)) & 0xFFu;
        cbytes[j] = c;
        occ += (c != 0);
        cnt += c;
    }
    ull v = ((ull)occ << 32) | (unsigned)cnt;

    ull incl = v;
#pragma unroll
    for (int off = 1; off < 32; off <<= 1) {
        ull n = __shfl_up_sync(0xffffffffu, incl, off);
        if (lane >= off) incl += n;
    }
    if (lane == 31) warp_tot[wid] = incl;
    __syncthreads();
    if (wid == 0) {
        ull w = (lane < 16) ? warp_tot[lane] : 0ull;
#pragma unroll
        for (int off = 1; off < 16; off <<= 1) {
            ull n = __shfl_up_sync(0xffffffffu, w, off);
            if (lane >= off) w += n;
        }
        if (lane < 16) warp_tot[lane] = w;
    }
    __syncthreads();
    ull excl_local = ((wid > 0) ? warp_tot[wid - 1] : 0ull) + incl - v;
    ull total = warp_tot[15];

    ull* state = reinterpret_cast<ull*>(g_histb + HWORDS);
    if (tid == 0) {
        if (bid == 0) {
            atomicExch(&state[0], FLAGI | total);
            sh_prefix = 0ull;
        } else {
            atomicExch(&state[bid], FLAGA | total);
        }
    }
    if (bid > 0 && wid == 0) {
        ull excl = 0;
        int idx = bid - 1;
        while (true) {
            int look = idx - lane;
            ull s = (look >= 0) ? atomicAdd(&state[look], 0ull) : FLAGI;
            unsigned f = (unsigned)(s >> 62);
            unsigned incm = __ballot_sync(0xffffffffu, f == 2u);
            unsigned zm = __ballot_sync(0xffffffffu, f == 0u);
            if (incm) {
                int fi = __ffs(incm) - 1;
                unsigned below = (fi == 0) ? 0u : ((1u << fi) - 1u);
                if (zm & below) continue;
                ull contrib = (lane <= fi) ? (s & VMASK) : 0ull;
                excl += warp_reduce_add(contrib);
                break;
            } else {
                if (zm) continue;
                excl += warp_reduce_add(s & VMASK);
                idx -= 32;
            }
        }
        if (lane == 0) {
            atomicExch(&state[bid], FLAGI | (excl + total));
            sh_prefix = excl;
        }
    }
    __syncthreads();
    ull prefix = sh_prefix;
    if (bid == NSCANBLK - 1 && tid == 0)
        g_U[0] = (int)((prefix + total) >> 32);

    int r = (int)((prefix >> 32) + (excl_local >> 32));
    int o = (int)((prefix & 0xFFFFFFFFull) + (excl_local & 0xFFFFFFFFull));
    int key0 = bid * (SCAN_T * 8) + tid * 8;
#pragma unroll
    for (int j = 0; j < 8; j++) {
        unsigned c = cbytes[j];
        if (c) {
            int key = key0 + j;
            g_rank[key] = r;
            g_start[r] = o;
            g_cursor[r] = o;
            grid_out[3 * r + 0] = (float)((key >> 14) & 127);
            grid_out[3 * r + 1] = (float)((key >> 7) & 127);
            grid_out[3 * r + 2] = (float)(key & 127);
            batch_out[r] = (float)(key >> 21);
            counts_out[r] = (float)c;
            r++;
            o += (int)c;
        }
    }
}

// ---------------- K3: scatter ----------------

__global__ void scatter_kernel(const float* __restrict__ coord,
                               float* __restrict__ coord_out,
                               float* __restrict__ cluster_out, int N) {
    int i = blockIdx.x * blockDim.x + threadIdx.x;
    if (i < N) {
        int c = g_rank[g_keys[i]];
        int pos = atomicAdd(&g_cursor[c], 1);
        g_pidx[pos] = i;
        cluster_out[i] = (float)c;
        atomicAdd(&coord_out[3 * c + 0], coord[3 * i + 0]);
        atomicAdd(&coord_out[3 * c + 1], coord[3 * i + 1]);
        atomicAdd(&coord_out[3 * c + 2], coord[3 * i + 2]);
    }
}

// ---------------- K4: HMMA GEMM, 512 threads ----------------
// smem words: A_hi 0, A_lo 4608, B_hi 9216, B_lo 13824 (stride 36 words/row)

#define GEMM_SMEM 73728

__device__ __forceinline__ void mma_bf16(float* c, const uint32_t* a,
                                         uint32_t b0, uint32_t b1) {
    asm volatile(
        "mma.sync.aligned.m16n8k16.row.col.f32.bf16.bf16.f32 "
        "{%0,%1,%2,%3}, {%4,%5,%6,%7}, {%8,%9}, {%0,%1,%2,%3};"
        : "+f"(c[0]), "+f"(c[1]), "+f"(c[2]), "+f"(c[3])
        : "r"(a[0]), "r"(a[1]), "r"(a[2]), "r"(a[3]), "r"(b0), "r"(b1));
}

__device__ __forceinline__ void ldsm4(uint32_t* r, uint32_t addr) {
    asm volatile(
        "ldmatrix.sync.aligned.m8n8.x4.shared.b16 {%0,%1,%2,%3}, [%4];"
        : "=r"(r[0]), "=r"(r[1]), "=r"(r[2]), "=r"(r[3]) : "r"(addr));
}

__device__ __forceinline__ uint32_t smem_u32(const void* p) {
    uint32_t a;
    asm("{ .reg .u64 t; cvta.to.shared.u64 t, %1; cvt.u32.u64 %0, t; }"
        : "=r"(a) : "l"(p));
    return a;
}

__device__ __forceinline__ uint32_t pack_bf16(float x0, float x1) {
    __nv_bfloat16 b0 = __float2bfloat16(x0), b1 = __float2bfloat16(x1);
    return ((uint32_t)__bfloat16_as_ushort(b1) << 16) | __bfloat16_as_ushort(b0);
}

__global__ __launch_bounds__(512, 2) void gemm_kernel(
    const float* __restrict__ bias, const float* __restrict__ feat,
    float* __restrict__ counts_out, float* __restrict__ coord_out,
    float* __restrict__ grid_out, float* __restrict__ batch_out,
    float* __restrict__ out, int N) {
    extern __shared__ uint32_t sm[];
    int tid = threadIdx.x;
    int rb = blockIdx.x * 128;
    int U = g_U[0];

    if (rb >= U) {  // pure padding tile
#pragma unroll
        for (int q = 0; q < 4; q++) {
            int t = q * 512 + tid;
            int row = rb + (t >> 4);
            if (row < N)
                reinterpret_cast<float4*>(out + (size_t)row * 128)[t & 15] =
                    make_float4(0.f, 0.f, 0.f, 0.f);
        }
        if (tid < 128) {
            int gr = rb + tid;
            if (gr < N) {
                batch_out[gr] = -1.0f;
                grid_out[3 * gr + 0] = 127.0f;
                grid_out[3 * gr + 1] = 127.0f;
                grid_out[3 * gr + 2] = 127.0f;
                counts_out[gr] = 0.0f;
            }
        }
        return;
    }

    // B tiles (L2-resident coalesced copy): 2304 uint4
    {
        uint4* dst = reinterpret_cast<uint4*>(sm + 9216);
#pragma unroll
        for (int q = 0; q < 5; q++) {
            int idx = q * 512 + tid;
            if (idx < 2304) dst[idx] = g_Bpack4[idx];
        }
    }

    // A: gather-mean; thread = (row, quarter of 64 ch) -> 16 ch each
    {
        int row = tid >> 2;
        int quarter = tid & 3;
        int gr = rb + row;
        float acc[16];
#pragma unroll
        for (int q = 0; q < 16; q++) acc[q] = 0.f;
        float inv = 0.f;
        if (gr < U) {
            int s = g_start[gr];
            int c = (int)counts_out[gr];
            inv = 1.0f / (float)c;
            int p = g_pidx[s];
            for (int j = 0; j < c; j++) {
                int pn = (j + 1 < c) ? g_pidx[s + j + 1] : 0;  // prefetch
                const float4* f =
                    reinterpret_cast<const float4*>(feat + (size_t)p * 64 + quarter * 16);
#pragma unroll
                for (int q = 0; q < 4; q++) {
                    float4 vv = f[q];
                    acc[4 * q + 0] += vv.x;
                    acc[4 * q + 1] += vv.y;
                    acc[4 * q + 2] += vv.z;
                    acc[4 * q + 3] += vv.w;
                }
                p = pn;
            }
        }
        int base = row * 36 + quarter * 8;
        uint4 hi0, hi1, lo0, lo1;
        uint32_t* hw = reinterpret_cast<uint32_t*>(&hi0);
        uint32_t* lw = reinterpret_cast<uint32_t*>(&lo0);
#pragma unroll
        for (int c2 = 0; c2 < 8; c2++) {
            float x0 = acc[2 * c2] * inv, x1 = acc[2 * c2 + 1] * inv;
            __nv_bfloat16 h0 = __float2bfloat16(x0), h1 = __float2bfloat16(x1);
            float r0 = x0 - __bfloat162float(h0);
            float r1 = x1 - __bfloat162float(h1);
            uint32_t hp = ((uint32_t)__bfloat16_as_ushort(h1) << 16) |
                          __bfloat16_as_ushort(h0);
            uint32_t lp = pack_bf16(r0, r1);
            if (c2 < 4) { hw[c2] = hp; lw[c2] = lp; }
            else { reinterpret_cast<uint32_t*>(&hi1)[c2 - 4] = hp;
                   reinterpret_cast<uint32_t*>(&lo1)[c2 - 4] = lp; }
        }
        *reinterpret_cast<uint4*>(sm + base) = hi0;
        *reinterpret_cast<uint4*>(sm + base + 4) = hi1;
        *reinterpret_cast<uint4*>(sm + 4608 + base) = lo0;
        *reinterpret_cast<uint4*>(sm + 4608 + base + 4) = lo1;
    }
    __syncthreads();

    // 16 warps: 4 along M (32 rows) x 4 along N (32 cols)
    int wid = tid >> 5, lane = tid & 31;
    int g = lane >> 2, tig = lane & 3;
    int wm = wid & 3, wn = wid >> 2;

    uint32_t smb = smem_u32(sm);
    int lrow = lane & 15, khalf = lane >> 4;
    uint32_t aAddr = smb + 4u * ((wm * 32 + lrow) * 36 + khalf * 4);
    uint32_t bAddr = smb + 36864u + 4u * ((wn * 32 + lrow) * 36 + khalf * 4);

    float c[2][4][4];
#pragma unroll
    for (int mt = 0; mt < 2; mt++)
#pragma unroll
        for (int nt = 0; nt < 4; nt++)
#pragma unroll
            for (int q = 0; q < 4; q++) c[mt][nt][q] = 0.f;

#pragma unroll
    for (int ks = 0; ks < 4; ks++) {
        uint32_t off = ks * 32u;
        uint32_t ah0[4], ah1[4], al0[4], al1[4];
        ldsm4(ah0, aAddr + off);
        ldsm4(ah1, aAddr + 2304u + off);
        ldsm4(al0, aAddr + 18432u + off);
        ldsm4(al1, aAddr + 18432u + 2304u + off);
        uint32_t bh0[4], bh1[4], bl0[4], bl1[4];
        ldsm4(bh0, bAddr + off);
        ldsm4(bh1, bAddr + 2304u + off);
        ldsm4(bl0, bAddr + 18432u + off);
        ldsm4(bl1, bAddr + 18432u + 2304u + off);
#pragma unroll
        for (int nt = 0; nt < 4; nt++) {
            uint32_t b0h = (nt < 2 ? bh0 : bh1)[nt & 1];
            uint32_t b1h = (nt < 2 ? bh0 : bh1)[2 + (nt & 1)];
            mma_bf16(c[0][nt], ah0, b0h, b1h);
            mma_bf16(c[1][nt], ah1, b0h, b1h);
            mma_bf16(c[0][nt], al0, b0h, b1h);
            mma_bf16(c[1][nt], al1, b0h, b1h);
            uint32_t b0l = (nt < 2 ? bl0 : bl1)[nt & 1];
            uint32_t b1l = (nt < 2 ? bl0 : bl1)[2 + (nt & 1)];
            mma_bf16(c[0][nt], ah0, b0l, b1l);
            mma_bf16(c[1][nt], ah1, b0l, b1l);
        }
    }

    // epilogue: permuted columns -> each lane owns 4 consecutive logical cols
    // logical col for (pair p, elem e, tig): wn*32 + 16p + 4tig + 2e
    float4 bv[2];
#pragma unroll
    for (int p = 0; p < 2; p++)
        bv[p] = *reinterpret_cast<const float4*>(bias + wn * 32 + 16 * p + 4 * tig);

#pragma unroll
    for (int mt = 0; mt < 2; mt++) {
#pragma unroll
        for (int half = 0; half < 2; half++) {
            int gr = rb + wm * 32 + mt * 16 + g + half * 8;
            if (gr >= N) continue;
            bool on = gr < U;
#pragma unroll
            for (int p = 0; p < 2; p++) {
                int col = wn * 32 + 16 * p + 4 * tig;
                float4 v;
                if (on) {
                    v.x = c[mt][2 * p][half * 2 + 0] + bv[p].x;
                    v.y = c[mt][2 * p][half * 2 + 1] + bv[p].y;
                    v.z = c[mt][2 * p + 1][half * 2 + 0] + bv[p].z;
                    v.w = c[mt][2 * p + 1][half * 2 + 1] + bv[p].w;
                } else {
                    v = make_float4(0.f, 0.f, 0.f, 0.f);
                }
                *reinterpret_cast<float4*>(out + (size_t)gr * 128 + col) = v;
            }
        }
    }

    // coord divide + padded-row defaults
    if (tid < 128) {
        int gr = rb + tid;
        if (gr < N) {
            if (gr < U) {
                float cnt = counts_out[gr];
                if (cnt > 1.5f) {
                    float inv = 1.0f / cnt;
                    coord_out[3 * gr + 0] *= inv;
                    coord_out[3 * gr + 1] *= inv;
                    coord_out[3 * gr + 2] *= inv;
                }
            } else {
                batch_out[gr] = -1.0f;
                grid_out[3 * gr + 0] = 127.0f;
                grid_out[3 * gr + 1] = 127.0f;
                grid_out[3 * gr + 2] = 127.0f;
                counts_out[gr] = 0.0f;
            }
        }
    }
}

// ---------------- launch ----------------

extern "C" void kernel_launch(void* const* d_in, const int* in_sizes, int n_in,
                              void* d_out, int out_size) {
    const float* feat       = (const float*)d_in[0];
    const float* coord      = (const float*)d_in[1];
    const int*   grid_coord = (const int*)d_in[2];
    const int*   batch      = (const int*)d_in[3];
    const float* W          = (const float*)d_in[4];
    const float* bias       = (const float*)d_in[5];
    int N = in_sizes[3];
    if (N > MAXN) N = MAXN;

    float* out         = (float*)d_out;
    float* feat_out    = out;
    float* coord_out   = out + (size_t)N * 128;
    float* grid_out    = coord_out + (size_t)N * 3;
    float* batch_out   = grid_out + (size_t)N * 3;
    float* cluster_out = batch_out + N;
    float* counts_out  = cluster_out + N;

    void* p_hist;
    cudaGetSymbolAddress(&p_hist, g_histb);
    cudaMemsetAsync(p_hist, 0, (size_t)(HWORDS + 2 * NSCANBLK) * 4);
    cudaMemsetAsync(coord_out, 0, (size_t)N * 3 * sizeof(float));

    int nb = (N + 255) / 256;
    keys_bpack_kernel<<<nb + 1, 256>>>(grid_coord, batch, W, N);
    scan_kernel<<<NSCANBLK, SCAN_T>>>(grid_out, batch_out, counts_out);
    scatter_kernel<<<nb, 256>>>(coord, coord_out, cluster_out, N);

    static int smem_set = 0;
    if (!smem_set) {
        cudaFuncSetAttribute(gemm_kernel,
                             cudaFuncAttributeMaxDynamicSharedMemorySize,
                             GEMM_SMEM);
        smem_set = 1;
    }
    gemm_kernel<<<(N + 127) / 128, 512, GEMM_SMEM>>>(
        bias, feat, counts_out, coord_out, grid_out, batch_out, feat_out, N);
}